// round 14
// baseline (speedup 1.0000x reference)
#include <cuda_runtime.h>
#include <cstdint>

#define T_STEPS 512
#define BATCH   64
#define INDIM   512
#define HID     1024
#define STRIPS  3072     // 1024 (W_hh0) + 1024 (W_ih1) + 1024 (W_hh1)
#define NKSEG   6
#define NITEMS  144      // 24 col-blocks (128 cols) x 6 k-segments
#define HSTRIDE 176      // smem row stride (floats)
#define PSTRIDE ((size_t)NKSEG * BATCH * STRIPS)   // one parts parity plane

typedef unsigned long long ull;

// ---------------- device scratch (static; no runtime allocation) ----------------
__device__ float g_preA[(size_t)T_STEPS * BATCH * HID];   // x @ W_ih0^T + b0, per step
__device__ float g_WTcat[(size_t)HID * STRIPS];           // [k][strip] transposed weights
__device__ float g_WT0[(size_t)INDIM * HID];              // [k][n] transposed W_ih0
__device__ float g_parts[2 * PSTRIDE];                    // parity double-buffered partials
__device__ float g_h0[BATCH * HID];
__device__ float g_h1[BATCH * HID];
__device__ unsigned g_barCount;
__device__ unsigned g_barGen;
__device__ unsigned g_doneA;    // GEMM items 0..95 completions (parts cb0..15; h0 readers)
__device__ unsigned g_doneB;    // GEMM items 96..143 completions (cb16..23; h1 readers)
__device__ unsigned g_doneL0;   // ln_row0 completions (64 per produced h0)
__device__ unsigned g_doneL1;   // ln_row1 completions (64 per produced h1)

// ---------------- packed f32x2 helpers (sm_103a FFMA2 path) ----------------
__device__ __forceinline__ ull fma2(ull a, ull b, ull c)
{
    ull d;
    asm("fma.rn.f32x2 %0, %1, %2, %3;" : "=l"(d) : "l"(a), "l"(b), "l"(c));
    return d;
}
__device__ __forceinline__ ull dup2(float x)
{
    ull d;
    asm("mov.b64 %0, {%1, %1};" : "=l"(d) : "f"(x));
    return d;
}

// ---------------- software grid barrier (used ONCE, after state init) ----------
__device__ __forceinline__ void gridsync(unsigned &gen, int nblk)
{
    __syncthreads();
    if (threadIdx.x == 0) {
        gen++;
        __threadfence();
        unsigned arrived = atomicAdd(&g_barCount, 1u) + 1u;
        if (arrived == (unsigned)nblk) {
            atomicExch(&g_barCount, 0u);
            __threadfence();
            atomicExch(&g_barGen, gen);
        } else {
            while (*((volatile unsigned*)&g_barGen) < gen) { }
        }
        __threadfence();
    }
    __syncthreads();
}

// wait until (counter - base) >= target (modular), acquire; block-wide release
__device__ __forceinline__ void waitCounter(unsigned* ctr, unsigned base, unsigned target)
{
    if (threadIdx.x == 0) {
        while (*((volatile unsigned*)ctr) - base < target) { }
        __threadfence();
    }
    __syncthreads();
}

// fused dual wait: poll BOTH counters in one spin (MLP=2 -> one detect latency,
// not two serial ones). target 0 is always satisfied (modular-safe).
__device__ __forceinline__ void waitCounter2(unsigned* cx, unsigned bx, unsigned tx_,
                                             unsigned* cy, unsigned by, unsigned ty_)
{
    if (threadIdx.x == 0) {
        for (;;) {
            unsigned vx = *((volatile unsigned*)cx);
            unsigned vy = *((volatile unsigned*)cy);
            if (vx - bx >= tx_ && vy - by >= ty_) break;
        }
        __threadfence();
    }
    __syncthreads();
}

// block-wide: all prior stores -> visible before counter increment
__device__ __forceinline__ void signalCtr(unsigned* ctr)
{
    __syncthreads();
    if (threadIdx.x == 0) { __threadfence(); atomicAdd(ctr, 1u); }
}

// ---------------- merged transpose: one launch, z selects matrix --------------
// z=0: W_hh0 -> g_WTcat[.., +0]    (K=HID)
// z=1: W_ih1 -> g_WTcat[.., +1024] (K=HID)
// z=2: W_hh1 -> g_WTcat[.., +2048] (K=HID)
// z=3: W_ih0 -> g_WT0              (K=INDIM; early-out for k0 >= INDIM)
__global__ void transposeAll(const float* __restrict__ w_hh0,
                             const float* __restrict__ w_ih1,
                             const float* __restrict__ w_hh1,
                             const float* __restrict__ w_ih0)
{
    __shared__ float sm[32][33];
    const int z = blockIdx.z;
    const float* src; float* dst; int K, dstStride, colOff;
    if (z == 0)      { src = w_hh0; dst = g_WTcat; K = HID;   dstStride = STRIPS; colOff = 0; }
    else if (z == 1) { src = w_ih1; dst = g_WTcat; K = HID;   dstStride = STRIPS; colOff = 1024; }
    else if (z == 2) { src = w_hh1; dst = g_WTcat; K = HID;   dstStride = STRIPS; colOff = 2048; }
    else             { src = w_ih0; dst = g_WT0;   K = INDIM; dstStride = HID;    colOff = 0; }

    int k0 = blockIdx.x * 32, c0 = blockIdx.y * 32;
    if (k0 >= K) return;
    int tx = threadIdx.x, ty = threadIdx.y;   // 32 x 8
#pragma unroll
    for (int i = 0; i < 32; i += 8)
        sm[ty + i][tx] = src[(size_t)(c0 + ty + i) * K + k0 + tx];
    __syncthreads();
#pragma unroll
    for (int i = 0; i < 32; i += 8)
        dst[(size_t)(k0 + ty + i) * dstStride + colOff + c0 + tx] = sm[tx][ty + i];
}

// ---------------- preA = x @ W_ih0^T + (b_ih0 + b_hh0) ----------------
// M = T*B = 32768, N = HID = 1024, K = INDIM = 512. Uses g_WT0 [k][n].
// FFMA2 microkernel: per-thread tile 4 rows x 4 cols = 4 x (2 packed f32x2).
__global__ void __launch_bounds__(256) preA_gemm(const float* __restrict__ x,
                                                 const float* __restrict__ bih,
                                                 const float* __restrict__ bhh)
{
    __shared__ float Xs[64][33];
    __shared__ float Ws[32][64];
    const int m0 = blockIdx.y * 64;
    const int n0 = blockIdx.x * 64;
    const int tid = threadIdx.x;
    const int tx = tid & 15, ty = tid >> 4;

    ull acc[4][2];
#pragma unroll
    for (int i = 0; i < 4; i++) { acc[i][0] = 0ull; acc[i][1] = 0ull; }

    for (int kt = 0; kt < INDIM; kt += 32) {
        {   // load X tile 64x32 (coalesced along k)
            int kq = (tid & 7) * 4, m = tid >> 3;  // 32 rows per pass
#pragma unroll
            for (int p = 0; p < 2; p++) {
                float4 v = *(const float4*)&x[(size_t)(m0 + m + p * 32) * INDIM + kt + kq];
                Xs[m + p * 32][kq + 0] = v.x; Xs[m + p * 32][kq + 1] = v.y;
                Xs[m + p * 32][kq + 2] = v.z; Xs[m + p * 32][kq + 3] = v.w;
            }
        }
        {   // load W tile 32x64 from g_WT0 (already k-major: coalesced)
            int n4 = (tid & 15) * 4, kk = tid >> 4;  // 16 rows per pass
#pragma unroll
            for (int p = 0; p < 2; p++) {
                float4 v = *(const float4*)&g_WT0[(size_t)(kt + kk + p * 16) * HID + n0 + n4];
                *(float4*)&Ws[kk + p * 16][n4] = v;
            }
        }
        __syncthreads();
#pragma unroll
        for (int kk = 0; kk < 32; kk++) {
            ulonglong2 bw = *(const ulonglong2*)&Ws[kk][tx * 4];
#pragma unroll
            for (int i = 0; i < 4; i++) {
                ull ad = dup2(Xs[ty * 4 + i][kk]);
                acc[i][0] = fma2(ad, bw.x, acc[i][0]);
                acc[i][1] = fma2(ad, bw.y, acc[i][1]);
            }
        }
        __syncthreads();
    }
    const int c0 = n0 + tx * 4;
    float4 bi = *(const float4*)&bih[c0];
    float4 bh = *(const float4*)&bhh[c0];
    float4 b0 = make_float4(bi.x + bh.x, bi.y + bh.y, bi.z + bh.z, bi.w + bh.w);
#pragma unroll
    for (int i = 0; i < 4; i++) {
        int row = m0 + ty * 4 + i;
        float2 a01 = *(float2*)&acc[i][0];
        float2 a23 = *(float2*)&acc[i][1];
        float4 o = make_float4(a01.x + b0.x, a01.y + b0.y, a23.x + b0.z, a23.y + b0.w);
        *(float4*)&g_preA[(size_t)row * HID + c0] = o;
    }
}

// ---------------- recurrent GEMM work item (FFMA2 + smem-staged h) ------------
// item = cb*6 + ks.  cb in [0,24): 128 strip-columns.  ks in [0,6): k-segment.
// strips [0,1024): W_hh0 (src h0) -> cb 0..7   (layer-0 items = 0..47)
// strips [1024,2048): W_ih1 (src h0) -> cb 8..15
// strips [2048,3072): W_hh1 (src h1) -> cb 16..23
// k-segments: 4 x 176 + 2 x 160 (KLEN compile-time).
// ADDP (cb<8, ks==0): fold the preA(tn) sub-row into the output; its DRAM
// latency hides behind the ~11K-cycle GEMM body.
template<int KLEN, bool ADDP>
__device__ __forceinline__ void gemm_item_t(float* s_h, float* pdst,
                                            int cb, int ks, int klo, int tn)
{
    const float* __restrict__ hs = (cb >= 16) ? g_h1 : g_h0;

    const int warp = threadIdx.x >> 5;
    const int lane = threadIdx.x & 31;
    const int r0 = warp * 8;
    const int c0 = cb * 128 + lane * 4;

    // early-issue preA loads (latency hidden behind staging + GEMM)
    float4 pa[ADDP ? 8 : 1];
    if (ADDP) {
#pragma unroll
        for (int r = 0; r < 8; r++)
            pa[r] = __ldcg((const float4*)&g_preA[((size_t)tn * BATCH + r0 + r) * HID + c0]);
    }

    // ---- stage h[0..63][klo..klo+KLEN) into smem ----
    // Exact-trip-count unrolled loop -> all independent LDG.128.cg front-batched
    // (MLP ~= NPASS), amortizing L2 latency maximally.
    constexpr int NF4   = KLEN / 4;        // 44 or 40 float4 per row (constexpr)
    constexpr int TOT   = 64 * NF4;        // 2816 or 2560 (both divisible by 256)
    constexpr int NPASS = TOT / 256;       // 11 or 10
#pragma unroll
    for (int p = 0; p < NPASS; p++) {
        int idx = threadIdx.x + p * 256;
        int row = idx / NF4;               // constexpr divisor -> mul/shift
        int col = idx - row * NF4;
        float4 v = __ldcg((const float4*)&hs[row * HID + klo + col * 4]);
        *(float4*)&s_h[row * HSTRIDE + col * 4] = v;
    }
    __syncthreads();

    ull acc[8][2];
#pragma unroll
    for (int r = 0; r < 8; r++) { acc[r][0] = 0ull; acc[r][1] = 0ull; }

#pragma unroll 2
    for (int cc = 0; cc < NF4; cc++) {
        const int k = klo + cc * 4;
        float4 hv[8];
#pragma unroll
        for (int r = 0; r < 8; r++)
            hv[r] = *(const float4*)&s_h[(r0 + r) * HSTRIDE + cc * 4];  // LDS.128 broadcast
#pragma unroll
        for (int kk = 0; kk < 4; kk++) {
            double2 wa = __ldg((const double2*)&g_WTcat[(size_t)(k + kk) * STRIPS + c0]);
            ull w0 = __double_as_longlong(wa.x);   // cols c0, c0+1
            ull w1 = __double_as_longlong(wa.y);   // cols c0+2, c0+3
#pragma unroll
            for (int r = 0; r < 8; r++) {
                float h = (kk == 0) ? hv[r].x : (kk == 1) ? hv[r].y
                        : (kk == 2) ? hv[r].z : hv[r].w;
                ull hd = dup2(h);
                acc[r][0] = fma2(hd, w0, acc[r][0]);
                acc[r][1] = fma2(hd, w1, acc[r][1]);
            }
        }
    }

#pragma unroll
    for (int r = 0; r < 8; r++) {
        float2 a0 = *(float2*)&acc[r][0];
        float2 a1 = *(float2*)&acc[r][1];
        if (ADDP) {
            a0.x += pa[r].x; a0.y += pa[r].y;
            a1.x += pa[r].z; a1.y += pa[r].w;
        }
        float4 o = make_float4(a0.x, a0.y, a1.x, a1.y);
        __stcg((float4*)&pdst[(size_t)(ks * BATCH + r0 + r) * STRIPS + c0], o);
    }
    // signalCtr's __syncthreads guards restaging and orders all stores
}

__device__ __forceinline__ void gemm_item(int item, int tn, int par)
{
    // single smem instance shared by all template instantiations
    __shared__ float s_h[64 * HSTRIDE];   // 45,056 B
    float* pdst = g_parts + (size_t)par * PSTRIDE;

    const int cb = item / 6;
    const int ks = item - cb * 6;
    if (ks < 4) {
        if (cb < 8 && ks == 0) gemm_item_t<176, true >(s_h, pdst, cb, ks, 0, tn);
        else                   gemm_item_t<176, false>(s_h, pdst, cb, ks, ks * 176, tn);
    } else {
        gemm_item_t<160, false>(s_h, pdst, cb, ks, 704 + (ks - 4) * 160, tn);
    }
}

// ---------------- block-wide reduction (sum, sumsq) over 256 threads ----------------
__device__ __forceinline__ void blockReduce2(float &s1, float &s2)
{
    __shared__ float sm[16];
#pragma unroll
    for (int o = 16; o > 0; o >>= 1) {
        s1 += __shfl_down_sync(0xffffffffu, s1, o);
        s2 += __shfl_down_sync(0xffffffffu, s2, o);
    }
    int w = threadIdx.x >> 5, l = threadIdx.x & 31;
    if (l == 0) { sm[w] = s1; sm[8 + w] = s2; }
    __syncthreads();
    float a = 0.0f, b = 0.0f;
#pragma unroll
    for (int i = 0; i < 8; i++) { a += sm[i]; b += sm[8 + i]; }
    __syncthreads();
    s1 = a; s2 = b;
}

// ---------------- LayerNorm + tanh, layer 0 row ----------------
// preA is already folded into the ks==0 partial by the GEMM phase.
__device__ __forceinline__ void ln_row0(int r, int par,
                                        const float* __restrict__ lnw,
                                        const float* __restrict__ lnb)
{
    const float* pb = g_parts + (size_t)par * PSTRIDE;
    const int c = threadIdx.x * 4;
    float4 w = *(const float4*)&lnw[c];
    float4 b = *(const float4*)&lnb[c];
    float4 v = __ldcg((const float4*)&pb[(size_t)r * STRIPS + c]);  // ks = 0
#pragma unroll
    for (int ks = 1; ks < NKSEG; ks++) {
        float4 p = __ldcg((const float4*)&pb[(size_t)(ks * BATCH + r) * STRIPS + c]);
        v.x += p.x; v.y += p.y; v.z += p.z; v.w += p.w;
    }
    float s1 = v.x + v.y + v.z + v.w;
    float s2 = v.x * v.x + v.y * v.y + v.z * v.z + v.w * v.w;
    blockReduce2(s1, s2);
    float mu  = s1 * (1.0f / HID);
    float var = s2 * (1.0f / HID) - mu * mu;
    float rstd = rsqrtf(var + 1e-5f);
    float4 h;
    h.x = tanhf((v.x - mu) * rstd * w.x + b.x);
    h.y = tanhf((v.y - mu) * rstd * w.y + b.y);
    h.z = tanhf((v.z - mu) * rstd * w.z + b.z);
    h.w = tanhf((v.w - mu) * rstd * w.w + b.w);
    __stcg((float4*)&g_h0[r * HID + c], h);
}

// ---------------- LayerNorm + tanh, layer 1 row (also writes out[t]) ----------------
__device__ __forceinline__ void ln_row1(int t, int r, int par,
                                        const float* __restrict__ bi,
                                        const float* __restrict__ bh,
                                        const float* __restrict__ lnw,
                                        const float* __restrict__ lnb,
                                        float* __restrict__ out)
{
    const float* pb = g_parts + (size_t)par * PSTRIDE;
    const int c = threadIdx.x * 4;
    float4 a = *(const float4*)&bi[c];
    float4 d = *(const float4*)&bh[c];
    float4 w = *(const float4*)&lnw[c];
    float4 b = *(const float4*)&lnb[c];
    float4 v = make_float4(a.x + d.x, a.y + d.y, a.z + d.z, a.w + d.w);
#pragma unroll
    for (int ks = 0; ks < NKSEG; ks++) {
        float4 p = __ldcg((const float4*)&pb[(size_t)(ks * BATCH + r) * STRIPS + 1024 + c]);
        float4 q = __ldcg((const float4*)&pb[(size_t)(ks * BATCH + r) * STRIPS + 2048 + c]);
        v.x += p.x + q.x; v.y += p.y + q.y; v.z += p.z + q.z; v.w += p.w + q.w;
    }
    float s1 = v.x + v.y + v.z + v.w;
    float s2 = v.x * v.x + v.y * v.y + v.z * v.z + v.w * v.w;
    blockReduce2(s1, s2);
    float mu  = s1 * (1.0f / HID);
    float var = s2 * (1.0f / HID) - mu * mu;
    float rstd = rsqrtf(var + 1e-5f);
    float4 h;
    h.x = tanhf((v.x - mu) * rstd * w.x + b.x);
    h.y = tanhf((v.y - mu) * rstd * w.y + b.y);
    h.z = tanhf((v.z - mu) * rstd * w.z + b.z);
    h.w = tanhf((v.w - mu) * rstd * w.w + b.w);
    __stcg((float4*)&g_h1[r * HID + c], h);
    *(float4*)&out[((size_t)t * BATCH + r) * HID + c] = h;
}

// ---------------- persistent recurrent kernel (barrier-free pipeline) ---------
// Fixed duty: block b runs GEMM item b (b<144; skipped for b<48 at t=T-1),
// blocks 0..63 run ln_row0, blocks 64..127 run ln_row1. Gates per iteration t:
//   GEMM cb0..7  : L0 >= 64(t+1)                     (h0(t) RAW + parity WAR)
//   GEMM cb8..15 : L0 >= 64(t+1), L1 >= 64(t-1)      (fused dual wait)
//   GEMM cb16..23: L1 >= 64t                         (h1(t-1) RAW + WAR)
//   ln_row0(t)   : dA >= 48+96(t+1)                  (parts + h0(t)-reader WAR)
//   ln_row1(t)   : dA >= 48+96t+(last?48:96) AND dB >= 48(t+1)  (fused dual wait)
//   tail         : L0 >= 64T AND L1 >= 64T           (fused dual wait)
// parts parity: loop iteration t -> t&1; prologue -> 1.
__global__ void __launch_bounds__(256, 1) rnn_persist(
    const float* __restrict__ hidden,
    const float* __restrict__ b_ih1, const float* __restrict__ b_hh1,
    const float* __restrict__ lnw0,  const float* __restrict__ lnb0,
    const float* __restrict__ lnw1,  const float* __restrict__ lnb1,
    float* __restrict__ out, int nblk)
{
    unsigned gen = 0, dAb = 0, dBb = 0, dL0b = 0, dL1b = 0;
    if (threadIdx.x == 0) {
        gen  = *((volatile unsigned*)&g_barGen);
        dAb  = *((volatile unsigned*)&g_doneA);    // bases read before any increment
        dBb  = *((volatile unsigned*)&g_doneB);
        dL0b = *((volatile unsigned*)&g_doneL0);
        dL1b = *((volatile unsigned*)&g_doneL1);
    }
    const int bid = blockIdx.x;

    // init recurrent state from `hidden` [2][B][H]
    for (int i = bid * 256 + threadIdx.x; i < 2 * BATCH * HID; i += nblk * 256) {
        float v = hidden[i];
        if (i < BATCH * HID) __stcg(&g_h0[i], v);
        else                 __stcg(&g_h1[i - BATCH * HID], v);
    }
    gridsync(gen, nblk);   // the ONLY full barrier: publishes init state + counter bases

    // prologue: pre0(0) = preA(0) + hidden0 @ W_hh0^T (items 0..47, parity 1)
    if (bid < 48) {
        gemm_item(bid, 0, 1);
        signalCtr(&g_doneA);
    }
    if (bid < 64) {
        waitCounter(&g_doneA, dAb, 48u);
        ln_row0(bid, 1, lnw0, lnb0);          // -> h0(0)
        signalCtr(&g_doneL0);
    }

    for (int t = 0; t < T_STEPS; t++) {
        const int par = t & 1;
        const bool last = (t == T_STEPS - 1);

        // ---- GEMM duty (item = bid, fixed) ----
        if (bid < NITEMS && !(last && bid < 48)) {
            const int cb = bid / 6;
            if (cb < 8) {
                waitCounter(&g_doneL0, dL0b, 64u * (unsigned)(t + 1));
            } else if (cb < 16) {
                waitCounter2(&g_doneL0, dL0b, 64u * (unsigned)(t + 1),
                             &g_doneL1, dL1b, (t >= 1) ? 64u * (unsigned)(t - 1) : 0u);
            } else {
                waitCounter(&g_doneL1, dL1b, 64u * (unsigned)t);
            }
            gemm_item(bid, t + 1, par);
            signalCtr(bid < 96 ? &g_doneA : &g_doneB);
        }

        // ---- LN duty ----
        if (bid < 64) {
            if (!last) {
                waitCounter(&g_doneA, dAb, 48u + 96u * (unsigned)(t + 1));
                ln_row0(bid, par, lnw0, lnb0);                     // -> h0(t+1)
                signalCtr(&g_doneL0);
            }
        } else if (bid < 128) {
            waitCounter2(&g_doneA, dAb, 48u + 96u * (unsigned)t + (last ? 48u : 96u),
                         &g_doneB, dBb, 48u * (unsigned)(t + 1));
            ln_row1(t, bid - 64, par, b_ih1, b_hh1, lnw1, lnb1, out);  // -> h1(t), out[t]
            signalCtr(&g_doneL1);
        }
    }

    // tail: h_fin = [h0(T-1), h1(T-1)] after ALL final LN completions
    waitCounter2(&g_doneL0, dL0b, 64u * (unsigned)T_STEPS,
                 &g_doneL1, dL1b, 64u * (unsigned)T_STEPS);
    const size_t tail = (size_t)T_STEPS * BATCH * HID;
    for (int i = bid * 256 + threadIdx.x; i < BATCH * HID; i += nblk * 256) {
        out[tail + i]               = __ldcg(&g_h0[i]);
        out[tail + BATCH * HID + i] = __ldcg(&g_h1[i]);
    }
}

// ---------------- host launcher ----------------
extern "C" void kernel_launch(void* const* d_in, const int* in_sizes, int n_in,
                              void* d_out, int out_size)
{
    const float* input = (const float*)d_in[0];
    const float* hidden = (const float*)d_in[1];
    const float* W_ih0 = (const float*)d_in[2];
    const float* W_hh0 = (const float*)d_in[3];
    const float* b_ih0 = (const float*)d_in[4];
    const float* b_hh0 = (const float*)d_in[5];
    const float* ln_w0 = (const float*)d_in[6];
    const float* ln_b0 = (const float*)d_in[7];
    const float* W_ih1 = (const float*)d_in[8];
    const float* W_hh1 = (const float*)d_in[9];
    const float* b_ih1 = (const float*)d_in[10];
    const float* b_hh1 = (const float*)d_in[11];
    const float* ln_w1 = (const float*)d_in[12];
    const float* ln_b1 = (const float*)d_in[13];
    float* out = (float*)d_out;

    int dev = 0, nsm = 148;
    cudaGetDevice(&dev);
    cudaDeviceGetAttribute(&nsm, cudaDevAttrMultiProcessorCount, dev);

    // 1) transpose all weights to k-major (single launch, z-indexed)
    transposeAll<<<dim3(HID / 32, HID / 32, 4), dim3(32, 8)>>>(W_hh0, W_ih1, W_hh1, W_ih0);

    // 2) preA = x @ W_ih0^T + b0 for all timesteps (parallel GEMM)
    preA_gemm<<<dim3(HID / 64, (T_STEPS * BATCH) / 64), 256>>>(input, b_ih0, b_hh0);

    // 3) persistent recurrent kernel
    rnn_persist<<<nsm, 256>>>(hidden, b_ih1, b_hh1, ln_w0, ln_b0, ln_w1, ln_b1, out, nsm);
}

// round 16
// speedup vs baseline: 1.0071x; 1.0071x over previous
#include <cuda_runtime.h>
#include <cuda_bf16.h>
#include <cstdint>

#define T_STEPS 512
#define BATCH   64
#define INDIM   512
#define HID     1024
#define STRIPS  3072     // 1024 (W_hh0) + 1024 (W_ih1) + 1024 (W_hh1)
#define NKSEG   6
#define NITEMS  144      // 24 col-blocks (128 cols) x 6 k-segments
#define HSB     184      // smem bf16 row stride (conflict-free padding)
#define PSTRIDE ((size_t)NKSEG * BATCH * STRIPS)   // one parts parity plane
#define NTILES_N 384     // 3072/8 n-tiles
#define NTILES_K 64      // 1024/16 k-tiles

typedef unsigned long long ull;
typedef unsigned int uint32;

// ---------------- device scratch (static; no runtime allocation) ----------------
__device__ float g_preA[(size_t)T_STEPS * BATCH * HID];   // x @ W_ih0^T + b0, per step
__device__ float g_WT0[(size_t)INDIM * HID];              // [k][n] transposed W_ih0 (preA)
__device__ uint2 g_WfragHi[(size_t)NTILES_N * NTILES_K * 32];  // bf16 hi fragments (b0,b1)
__device__ uint2 g_WfragLo[(size_t)NTILES_N * NTILES_K * 32];  // bf16 lo fragments
__device__ float g_parts[2 * PSTRIDE];                    // parity double-buffered partials
__device__ float g_h0[BATCH * HID];
__device__ float g_h1[BATCH * HID];
__device__ unsigned g_barCount;
__device__ unsigned g_barGen;
__device__ unsigned g_doneA;    // GEMM items 0..95 completions
__device__ unsigned g_doneB;    // GEMM items 96..143 completions
__device__ unsigned g_doneL0;   // ln_row0 completions
__device__ unsigned g_doneL1;   // ln_row1 completions

// ---------------- packed f32x2 helpers (preA kernel only) ----------------
__device__ __forceinline__ ull fma2(ull a, ull b, ull c)
{
    ull d;
    asm("fma.rn.f32x2 %0, %1, %2, %3;" : "=l"(d) : "l"(a), "l"(b), "l"(c));
    return d;
}
__device__ __forceinline__ ull dup2(float x)
{
    ull d;
    asm("mov.b64 %0, {%1, %1};" : "=l"(d) : "f"(x));
    return d;
}

// ---------------- mma.sync m16n8k16 bf16 (fp32 accumulate, in place) ----------
__device__ __forceinline__ void mma_bf16(float* c, uint32 a0, uint32 a1, uint32 a2,
                                         uint32 a3, uint32 b0, uint32 b1)
{
    asm volatile(
        "mma.sync.aligned.m16n8k16.row.col.f32.bf16.bf16.f32 "
        "{%0,%1,%2,%3}, {%4,%5,%6,%7}, {%8,%9}, {%0,%1,%2,%3};"
        : "+f"(c[0]), "+f"(c[1]), "+f"(c[2]), "+f"(c[3])
        : "r"(a0), "r"(a1), "r"(a2), "r"(a3), "r"(b0), "r"(b1));
}

__device__ __forceinline__ __nv_bfloat162 pack2(float a, float b)
{
    __nv_bfloat162 r;
    r.x = __float2bfloat16(a);
    r.y = __float2bfloat16(b);
    return r;
}

// ---------------- software grid barrier (used ONCE, after state init) ----------
__device__ __forceinline__ void gridsync(unsigned &gen, int nblk)
{
    __syncthreads();
    if (threadIdx.x == 0) {
        gen++;
        __threadfence();
        unsigned arrived = atomicAdd(&g_barCount, 1u) + 1u;
        if (arrived == (unsigned)nblk) {
            atomicExch(&g_barCount, 0u);
            __threadfence();
            atomicExch(&g_barGen, gen);
        } else {
            while (*((volatile unsigned*)&g_barGen) < gen) { }
        }
        __threadfence();
    }
    __syncthreads();
}

__device__ __forceinline__ void waitCounter(unsigned* ctr, unsigned base, unsigned target)
{
    if (threadIdx.x == 0) {
        while (*((volatile unsigned*)ctr) - base < target) { }
        __threadfence();
    }
    __syncthreads();
}

__device__ __forceinline__ void waitCounter2(unsigned* cx, unsigned bx, unsigned tx_,
                                             unsigned* cy, unsigned by, unsigned ty_)
{
    if (threadIdx.x == 0) {
        for (;;) {
            unsigned vx = *((volatile unsigned*)cx);
            unsigned vy = *((volatile unsigned*)cy);
            if (vx - bx >= tx_ && vy - by >= ty_) break;
        }
        __threadfence();
    }
    __syncthreads();
}

__device__ __forceinline__ void signalCtr(unsigned* ctr)
{
    __syncthreads();
    if (threadIdx.x == 0) { __threadfence(); atomicAdd(ctr, 1u); }
}

// ---------------- transpose W_ih0 -> g_WT0 [k][n]  (preA operand) -------------
__global__ void transposeW0(const float* __restrict__ src)   // src: [HID][INDIM]
{
    __shared__ float sm[32][33];
    int k0 = blockIdx.x * 32, c0 = blockIdx.y * 32;
    int tx = threadIdx.x, ty = threadIdx.y;   // 32 x 8
#pragma unroll
    for (int i = 0; i < 32; i += 8)
        sm[ty + i][tx] = src[(size_t)(c0 + ty + i) * INDIM + k0 + tx];
    __syncthreads();
#pragma unroll
    for (int i = 0; i < 32; i += 8)
        g_WT0[(size_t)(k0 + ty + i) * HID + c0 + tx] = sm[tx][ty + i];
}

// ---------------- build bf16 hi/lo weight fragments ---------------------------
// Fragment-major layout: index = ((nt*64 + kt)*32 + lane); each entry uint2{b0,b1}.
// b0 = bf16x2 { W[n][k], W[n][k+1] }, b1 = { W[n][k+8], W[n][k+9] },
// n = nt*8 + lane/4, k = kt*16 + (lane%4)*2.
// Rows: n<1024 -> W_hh0, n<2048 -> W_ih1, else W_hh1.
__global__ void makeWfrag(const float* __restrict__ w_hh0,
                          const float* __restrict__ w_ih1,
                          const float* __restrict__ w_hh1)
{
    int id = blockIdx.x * 256 + threadIdx.x;        // [0, 384*64*32)
    int lane = id & 31;
    int kt = (id >> 5) & 63;
    int nt = id >> 11;
    int n = nt * 8 + (lane >> 2);
    int k = kt * 16 + (lane & 3) * 2;
    const float* W = (n < 1024) ? w_hh0 + (size_t)n * HID
                   : (n < 2048) ? w_ih1 + (size_t)(n - 1024) * HID
                                : w_hh1 + (size_t)(n - 2048) * HID;
    float w0 = W[k], w1 = W[k + 1], w2 = W[k + 8], w3 = W[k + 9];
    __nv_bfloat162 h0 = pack2(w0, w1), h1 = pack2(w2, w3);
    float l0 = w0 - __bfloat162float(h0.x), l1 = w1 - __bfloat162float(h0.y);
    float l2 = w2 - __bfloat162float(h1.x), l3 = w3 - __bfloat162float(h1.y);
    __nv_bfloat162 q0 = pack2(l0, l1), q1 = pack2(l2, l3);
    g_WfragHi[id] = make_uint2(*(uint32*)&h0, *(uint32*)&h1);
    g_WfragLo[id] = make_uint2(*(uint32*)&q0, *(uint32*)&q1);
}

// ---------------- preA = x @ W_ih0^T + (b_ih0 + b_hh0) ----------------
__global__ void __launch_bounds__(256) preA_gemm(const float* __restrict__ x,
                                                 const float* __restrict__ bih,
                                                 const float* __restrict__ bhh)
{
    __shared__ float Xs[64][33];
    __shared__ float Ws[32][64];
    const int m0 = blockIdx.y * 64;
    const int n0 = blockIdx.x * 64;
    const int tid = threadIdx.x;
    const int tx = tid & 15, ty = tid >> 4;

    ull acc[4][2];
#pragma unroll
    for (int i = 0; i < 4; i++) { acc[i][0] = 0ull; acc[i][1] = 0ull; }

    for (int kt = 0; kt < INDIM; kt += 32) {
        {
            int kq = (tid & 7) * 4, m = tid >> 3;
#pragma unroll
            for (int p = 0; p < 2; p++) {
                float4 v = *(const float4*)&x[(size_t)(m0 + m + p * 32) * INDIM + kt + kq];
                Xs[m + p * 32][kq + 0] = v.x; Xs[m + p * 32][kq + 1] = v.y;
                Xs[m + p * 32][kq + 2] = v.z; Xs[m + p * 32][kq + 3] = v.w;
            }
        }
        {
            int n4 = (tid & 15) * 4, kk = tid >> 4;
#pragma unroll
            for (int p = 0; p < 2; p++) {
                float4 v = *(const float4*)&g_WT0[(size_t)(kt + kk + p * 16) * HID + n0 + n4];
                *(float4*)&Ws[kk + p * 16][n4] = v;
            }
        }
        __syncthreads();
#pragma unroll
        for (int kk = 0; kk < 32; kk++) {
            ulonglong2 bw = *(const ulonglong2*)&Ws[kk][tx * 4];
#pragma unroll
            for (int i = 0; i < 4; i++) {
                ull ad = dup2(Xs[ty * 4 + i][kk]);
                acc[i][0] = fma2(ad, bw.x, acc[i][0]);
                acc[i][1] = fma2(ad, bw.y, acc[i][1]);
            }
        }
        __syncthreads();
    }
    const int c0 = n0 + tx * 4;
    float4 bi = *(const float4*)&bih[c0];
    float4 bh = *(const float4*)&bhh[c0];
    float4 b0 = make_float4(bi.x + bh.x, bi.y + bh.y, bi.z + bh.z, bi.w + bh.w);
#pragma unroll
    for (int i = 0; i < 4; i++) {
        int row = m0 + ty * 4 + i;
        float2 a01 = *(float2*)&acc[i][0];
        float2 a23 = *(float2*)&acc[i][1];
        float4 o = make_float4(a01.x + b0.x, a01.y + b0.y, a23.x + b0.z, a23.y + b0.w);
        *(float4*)&g_preA[(size_t)row * HID + c0] = o;
    }
}

// ---------------- recurrent GEMM work item (bf16-split tensor-core) -----------
// item = cb*6 + ks.  cb in [0,24): 128 strip-columns.  ks in [0,6): k-segment.
// cb 0..7: W_hh0 (h0);  cb 8..15: W_ih1 (h0);  cb 16..23: W_hh1 (h1).
// k-segments: 4 x 176 + 2 x 160 (div by 16).
// 3-pass bf16 split: D = Ahi*Bhi + Ahi*Blo + Alo*Bhi (fp32 accumulate).
// Warp layout: 8 warps = 4 m-tiles(16 rows) x 2 n-halves(64 cols).
// ADDP (cb<8, ks==0): fold preA(tn) into output.
template<int KLEN, bool ADDP>
__device__ __forceinline__ void gemm_item_t(__nv_bfloat16* s_hhi, __nv_bfloat16* s_hlo,
                                            float* pdst, int cb, int ks, int klo, int tn)
{
    const float* __restrict__ hs = (cb >= 16) ? g_h1 : g_h0;
    const int tid  = threadIdx.x;
    const int lane = tid & 31;
    const int warp = tid >> 5;
    const int qr = lane >> 2;           // 0..7
    const int qk = (lane & 3) * 2;      // 0,2,4,6
    const int m0 = (warp & 3) * 16;     // m-tile base (batch rows)
    const int nh = (warp >> 2) * 64;    // n-half within cb tile
    const int cbase = cb * 128 + nh;    // global strip col base for this warp

    // early-issue preA loads (ADDP only): C-frag positions for all 8 n-tiles
    float2 paL[ADDP ? 8 : 1], paH[ADDP ? 8 : 1];
    if (ADDP) {
#pragma unroll
        for (int nt = 0; nt < 8; nt++) {
            const float* pb = &g_preA[((size_t)tn * BATCH) * HID + cbase + nt * 8 + qk];
            paL[nt] = __ldcg((const float2*)&pb[(size_t)(m0 + qr) * HID]);
            paH[nt] = __ldcg((const float2*)&pb[(size_t)(m0 + qr + 8) * HID]);
        }
    }

    // ---- stage h[0..63][klo..klo+KLEN) into smem as bf16 hi/lo planes ----
    constexpr int NF4   = KLEN / 4;
    constexpr int NPASS = (64 * NF4) / 256;   // 11 or 10
#pragma unroll
    for (int p = 0; p < NPASS; p++) {
        int idx = tid + p * 256;
        int row = idx / NF4;
        int col = (idx - row * NF4) * 4;      // bf16/float index within window
        float4 v = __ldcg((const float4*)&hs[row * HID + klo + col]);
        __nv_bfloat162 h01 = pack2(v.x, v.y), h23 = pack2(v.z, v.w);
        __nv_bfloat162 l01 = pack2(v.x - __bfloat162float(h01.x),
                                   v.y - __bfloat162float(h01.y));
        __nv_bfloat162 l23 = pack2(v.z - __bfloat162float(h23.x),
                                   v.w - __bfloat162float(h23.y));
        *(__nv_bfloat162*)&s_hhi[row * HSB + col]     = h01;
        *(__nv_bfloat162*)&s_hhi[row * HSB + col + 2] = h23;
        *(__nv_bfloat162*)&s_hlo[row * HSB + col]     = l01;
        *(__nv_bfloat162*)&s_hlo[row * HSB + col + 2] = l23;
    }
    __syncthreads();

    // ---- tensor-core mainloop ----
    constexpr int NF16 = KLEN / 16;           // 11 or 10
    const int ktg0 = klo / 16;                // global k-tile base
    const int ntg0 = cb * 16 + (nh >> 3);     // global n-tile base for this warp

    float acc[8][4];
#pragma unroll
    for (int nt = 0; nt < 8; nt++)
#pragma unroll
        for (int j = 0; j < 4; j++) acc[nt][j] = 0.0f;

#pragma unroll 1
    for (int kt = 0; kt < NF16; kt++) {
        const int kk = kt * 16;
        // A fragments (m16 x k16), hi and lo, from smem (conflict-free banks)
        uint32 a0h = *(const uint32*)&s_hhi[(m0 + qr) * HSB + kk + qk];
        uint32 a1h = *(const uint32*)&s_hhi[(m0 + qr + 8) * HSB + kk + qk];
        uint32 a2h = *(const uint32*)&s_hhi[(m0 + qr) * HSB + kk + qk + 8];
        uint32 a3h = *(const uint32*)&s_hhi[(m0 + qr + 8) * HSB + kk + qk + 8];
        uint32 a0l = *(const uint32*)&s_hlo[(m0 + qr) * HSB + kk + qk];
        uint32 a1l = *(const uint32*)&s_hlo[(m0 + qr + 8) * HSB + kk + qk];
        uint32 a2l = *(const uint32*)&s_hlo[(m0 + qr) * HSB + kk + qk + 8];
        uint32 a3l = *(const uint32*)&s_hlo[(m0 + qr + 8) * HSB + kk + qk + 8];
        const size_t fbase = ((size_t)ntg0 * NTILES_K + (ktg0 + kt)) * 32 + lane;
#pragma unroll
        for (int nt = 0; nt < 8; nt++) {
            uint2 bh = __ldg(&g_WfragHi[fbase + (size_t)nt * NTILES_K * 32]);
            uint2 bl = __ldg(&g_WfragLo[fbase + (size_t)nt * NTILES_K * 32]);
            mma_bf16(acc[nt], a0h, a1h, a2h, a3h, bh.x, bh.y);   // hi*hi
            mma_bf16(acc[nt], a0h, a1h, a2h, a3h, bl.x, bl.y);   // hi*lo
            mma_bf16(acc[nt], a0l, a1l, a2l, a3l, bh.x, bh.y);   // lo*hi
        }
    }

    // ---- epilogue: write partials (C-frag scatter; rows are batch rows) ----
#pragma unroll
    for (int nt = 0; nt < 8; nt++) {
        float2 s0 = make_float2(acc[nt][0], acc[nt][1]);
        float2 s1 = make_float2(acc[nt][2], acc[nt][3]);
        if (ADDP) {
            s0.x += paL[nt].x; s0.y += paL[nt].y;
            s1.x += paH[nt].x; s1.y += paH[nt].y;
        }
        float* pb = &pdst[(size_t)(ks * BATCH) * STRIPS + cbase + nt * 8 + qk];
        __stcg((float2*)&pb[(size_t)(m0 + qr) * STRIPS], s0);
        __stcg((float2*)&pb[(size_t)(m0 + qr + 8) * STRIPS], s1);
    }
    // signalCtr's __syncthreads guards restaging and orders all stores
}

__device__ __forceinline__ void gemm_item(int item, int tn, int par)
{
    // single smem instance shared by all template instantiations (47,104 B)
    __shared__ __nv_bfloat16 s_hhi[64 * HSB];
    __shared__ __nv_bfloat16 s_hlo[64 * HSB];
    float* pdst = g_parts + (size_t)par * PSTRIDE;

    const int cb = item / 6;
    const int ks = item - cb * 6;
    if (ks < 4) {
        if (cb < 8 && ks == 0) gemm_item_t<176, true >(s_hhi, s_hlo, pdst, cb, ks, 0, tn);
        else                   gemm_item_t<176, false>(s_hhi, s_hlo, pdst, cb, ks, ks * 176, tn);
    } else {
        gemm_item_t<160, false>(s_hhi, s_hlo, pdst, cb, ks, 704 + (ks - 4) * 160, tn);
    }
}

// ---------------- block-wide reduction (sum, sumsq) over 256 threads ----------------
__device__ __forceinline__ void blockReduce2(float &s1, float &s2)
{
    __shared__ float sm[16];
#pragma unroll
    for (int o = 16; o > 0; o >>= 1) {
        s1 += __shfl_down_sync(0xffffffffu, s1, o);
        s2 += __shfl_down_sync(0xffffffffu, s2, o);
    }
    int w = threadIdx.x >> 5, l = threadIdx.x & 31;
    if (l == 0) { sm[w] = s1; sm[8 + w] = s2; }
    __syncthreads();
    float a = 0.0f, b = 0.0f;
#pragma unroll
    for (int i = 0; i < 8; i++) { a += sm[i]; b += sm[8 + i]; }
    __syncthreads();
    s1 = a; s2 = b;
}

// ---------------- LayerNorm + tanh, layer 0 row ----------------
__device__ __forceinline__ void ln_row0(int r, int par,
                                        const float* __restrict__ lnw,
                                        const float* __restrict__ lnb)
{
    const float* pb = g_parts + (size_t)par * PSTRIDE;
    const int c = threadIdx.x * 4;
    float4 w = *(const float4*)&lnw[c];
    float4 b = *(const float4*)&lnb[c];
    float4 v = __ldcg((const float4*)&pb[(size_t)r * STRIPS + c]);  // ks = 0 (has preA)
#pragma unroll
    for (int ks = 1; ks < NKSEG; ks++) {
        float4 p = __ldcg((const float4*)&pb[(size_t)(ks * BATCH + r) * STRIPS + c]);
        v.x += p.x; v.y += p.y; v.z += p.z; v.w += p.w;
    }
    float s1 = v.x + v.y + v.z + v.w;
    float s2 = v.x * v.x + v.y * v.y + v.z * v.z + v.w * v.w;
    blockReduce2(s1, s2);
    float mu  = s1 * (1.0f / HID);
    float var = s2 * (1.0f / HID) - mu * mu;
    float rstd = rsqrtf(var + 1e-5f);
    float4 h;
    h.x = tanhf((v.x - mu) * rstd * w.x + b.x);
    h.y = tanhf((v.y - mu) * rstd * w.y + b.y);
    h.z = tanhf((v.z - mu) * rstd * w.z + b.z);
    h.w = tanhf((v.w - mu) * rstd * w.w + b.w);
    __stcg((float4*)&g_h0[r * HID + c], h);
}

// ---------------- LayerNorm + tanh, layer 1 row (also writes out[t]) ----------------
__device__ __forceinline__ void ln_row1(int t, int r, int par,
                                        const float* __restrict__ bi,
                                        const float* __restrict__ bh,
                                        const float* __restrict__ lnw,
                                        const float* __restrict__ lnb,
                                        float* __restrict__ out)
{
    const float* pb = g_parts + (size_t)par * PSTRIDE;
    const int c = threadIdx.x * 4;
    float4 a = *(const float4*)&bi[c];
    float4 d = *(const float4*)&bh[c];
    float4 w = *(const float4*)&lnw[c];
    float4 b = *(const float4*)&lnb[c];
    float4 v = make_float4(a.x + d.x, a.y + d.y, a.z + d.z, a.w + d.w);
#pragma unroll
    for (int ks = 0; ks < NKSEG; ks++) {
        float4 p = __ldcg((const float4*)&pb[(size_t)(ks * BATCH + r) * STRIPS + 1024 + c]);
        float4 q = __ldcg((const float4*)&pb[(size_t)(ks * BATCH + r) * STRIPS + 2048 + c]);
        v.x += p.x + q.x; v.y += p.y + q.y; v.z += p.z + q.z; v.w += p.w + q.w;
    }
    float s1 = v.x + v.y + v.z + v.w;
    float s2 = v.x * v.x + v.y * v.y + v.z * v.z + v.w * v.w;
    blockReduce2(s1, s2);
    float mu  = s1 * (1.0f / HID);
    float var = s2 * (1.0f / HID) - mu * mu;
    float rstd = rsqrtf(var + 1e-5f);
    float4 h;
    h.x = tanhf((v.x - mu) * rstd * w.x + b.x);
    h.y = tanhf((v.y - mu) * rstd * w.y + b.y);
    h.z = tanhf((v.z - mu) * rstd * w.z + b.z);
    h.w = tanhf((v.w - mu) * rstd * w.w + b.w);
    __stcg((float4*)&g_h1[r * HID + c], h);
    *(float4*)&out[((size_t)t * BATCH + r) * HID + c] = h;
}

// ---------------- persistent recurrent kernel (barrier-free pipeline) ---------
// (protocol identical to the audited R14 version that passed at 9528us)
__global__ void __launch_bounds__(256, 1) rnn_persist(
    const float* __restrict__ hidden,
    const float* __restrict__ b_ih1, const float* __restrict__ b_hh1,
    const float* __restrict__ lnw0,  const float* __restrict__ lnb0,
    const float* __restrict__ lnw1,  const float* __restrict__ lnb1,
    float* __restrict__ out, int nblk)
{
    unsigned gen = 0, dAb = 0, dBb = 0, dL0b = 0, dL1b = 0;
    if (threadIdx.x == 0) {
        gen  = *((volatile unsigned*)&g_barGen);
        dAb  = *((volatile unsigned*)&g_doneA);
        dBb  = *((volatile unsigned*)&g_doneB);
        dL0b = *((volatile unsigned*)&g_doneL0);
        dL1b = *((volatile unsigned*)&g_doneL1);
    }
    const int bid = blockIdx.x;

    for (int i = bid * 256 + threadIdx.x; i < 2 * BATCH * HID; i += nblk * 256) {
        float v = hidden[i];
        if (i < BATCH * HID) __stcg(&g_h0[i], v);
        else                 __stcg(&g_h1[i - BATCH * HID], v);
    }
    gridsync(gen, nblk);

    // prologue: pre0(0) (items 0..47, parity 1)
    if (bid < 48) {
        gemm_item(bid, 0, 1);
        signalCtr(&g_doneA);
    }
    if (bid < 64) {
        waitCounter(&g_doneA, dAb, 48u);
        ln_row0(bid, 1, lnw0, lnb0);
        signalCtr(&g_doneL0);
    }

    for (int t = 0; t < T_STEPS; t++) {
        const int par = t & 1;
        const bool last = (t == T_STEPS - 1);

        if (bid < NITEMS && !(last && bid < 48)) {
            const int cb = bid / 6;
            if (cb < 8) {
                waitCounter(&g_doneL0, dL0b, 64u * (unsigned)(t + 1));
            } else if (cb < 16) {
                waitCounter2(&g_doneL0, dL0b, 64u * (unsigned)(t + 1),
                             &g_doneL1, dL1b, (t >= 1) ? 64u * (unsigned)(t - 1) : 0u);
            } else {
                waitCounter(&g_doneL1, dL1b, 64u * (unsigned)t);
            }
            gemm_item(bid, t + 1, par);
            signalCtr(bid < 96 ? &g_doneA : &g_doneB);
        }

        if (bid < 64) {
            if (!last) {
                waitCounter(&g_doneA, dAb, 48u + 96u * (unsigned)(t + 1));
                ln_row0(bid, par, lnw0, lnb0);
                signalCtr(&g_doneL0);
            }
        } else if (bid < 128) {
            waitCounter2(&g_doneA, dAb, 48u + 96u * (unsigned)t + (last ? 48u : 96u),
                         &g_doneB, dBb, 48u * (unsigned)(t + 1));
            ln_row1(t, bid - 64, par, b_ih1, b_hh1, lnw1, lnb1, out);
            signalCtr(&g_doneL1);
        }
    }

    waitCounter2(&g_doneL0, dL0b, 64u * (unsigned)T_STEPS,
                 &g_doneL1, dL1b, 64u * (unsigned)T_STEPS);
    const size_t tail = (size_t)T_STEPS * BATCH * HID;
    for (int i = bid * 256 + threadIdx.x; i < BATCH * HID; i += nblk * 256) {
        out[tail + i]               = __ldcg(&g_h0[i]);
        out[tail + BATCH * HID + i] = __ldcg(&g_h1[i]);
    }
}

// ---------------- host launcher ----------------
extern "C" void kernel_launch(void* const* d_in, const int* in_sizes, int n_in,
                              void* d_out, int out_size)
{
    const float* input = (const float*)d_in[0];
    const float* hidden = (const float*)d_in[1];
    const float* W_ih0 = (const float*)d_in[2];
    const float* W_hh0 = (const float*)d_in[3];
    const float* b_ih0 = (const float*)d_in[4];
    const float* b_hh0 = (const float*)d_in[5];
    const float* ln_w0 = (const float*)d_in[6];
    const float* ln_b0 = (const float*)d_in[7];
    const float* W_ih1 = (const float*)d_in[8];
    const float* W_hh1 = (const float*)d_in[9];
    const float* b_ih1 = (const float*)d_in[10];
    const float* b_hh1 = (const float*)d_in[11];
    const float* ln_w1 = (const float*)d_in[12];
    const float* ln_b1 = (const float*)d_in[13];
    float* out = (float*)d_out;

    int dev = 0, nsm = 148;
    cudaGetDevice(&dev);
    cudaDeviceGetAttribute(&nsm, cudaDevAttrMultiProcessorCount, dev);

    // 1) weight prep: transpose W_ih0 (preA) + bf16 hi/lo fragments (recurrent)
    transposeW0<<<dim3(INDIM / 32, HID / 32), dim3(32, 8)>>>(W_ih0);
    makeWfrag<<<(NTILES_N * NTILES_K * 32) / 256, 256>>>(W_hh0, W_ih1, W_hh1);

    // 2) preA = x @ W_ih0^T + b0 for all timesteps (parallel GEMM)
    preA_gemm<<<dim3(HID / 64, (T_STEPS * BATCH) / 64), 256>>>(input, b_ih0, b_hh0);

    // 3) persistent recurrent kernel
    rnn_persist<<<nsm, 256>>>(hidden, b_ih1, b_hh1, ln_w0, ln_b0, ln_w1, ln_b1, out, nsm);
}

// round 17
// speedup vs baseline: 1.3765x; 1.3668x over previous
#include <cuda_runtime.h>
#include <cuda_bf16.h>
#include <cstdint>

#define T_STEPS 512
#define BATCH   64
#define INDIM   512
#define HID     1024
#define STRIPS  3072     // 1024 (W_hh0) + 1024 (W_ih1) + 1024 (W_hh1)
#define NKSEG   6
#define NITEMS  144      // 24 col-blocks (128 cols) x 6 k-segments
#define HSB     184      // smem bf16 row stride (conflict-free padding)
#define PSTRIDE ((size_t)NKSEG * BATCH * STRIPS)   // one parts parity plane
#define NTILES_N 384     // 3072/8 n-tiles
#define NTILES_K 64      // 1024/16 k-tiles

typedef unsigned long long ull;
typedef unsigned int uint32;

// ---------------- device scratch (static; no runtime allocation) ----------------
__device__ float g_preA[(size_t)T_STEPS * BATCH * HID];   // x @ W_ih0^T + b0, per step
__device__ float g_WT0[(size_t)INDIM * HID];              // [k][n] transposed W_ih0 (preA)
__device__ uint4 g_Wfrag[(size_t)NTILES_N * NTILES_K * 32]; // bf16 frags {hi0,hi1,lo0,lo1}
__device__ float g_parts[2 * PSTRIDE];                    // parity double-buffered partials
__device__ float g_h0[BATCH * HID];
__device__ float g_h1[BATCH * HID];
__device__ unsigned g_barCount;
__device__ unsigned g_barGen;
__device__ unsigned g_doneA;    // GEMM items 0..95 completions
__device__ unsigned g_doneB;    // GEMM items 96..143 completions
__device__ unsigned g_doneL0;   // ln_row0 completions
__device__ unsigned g_doneL1;   // ln_row1 completions

// ---------------- packed f32x2 helpers (preA kernel only) ----------------
__device__ __forceinline__ ull fma2(ull a, ull b, ull c)
{
    ull d;
    asm("fma.rn.f32x2 %0, %1, %2, %3;" : "=l"(d) : "l"(a), "l"(b), "l"(c));
    return d;
}
__device__ __forceinline__ ull dup2(float x)
{
    ull d;
    asm("mov.b64 %0, {%1, %1};" : "=l"(d) : "f"(x));
    return d;
}

// ---------------- mma.sync m16n8k16 bf16 (fp32 accumulate, in place) ----------
__device__ __forceinline__ void mma_bf16(float* c, uint32 a0, uint32 a1, uint32 a2,
                                         uint32 a3, uint32 b0, uint32 b1)
{
    asm volatile(
        "mma.sync.aligned.m16n8k16.row.col.f32.bf16.bf16.f32 "
        "{%0,%1,%2,%3}, {%4,%5,%6,%7}, {%8,%9}, {%0,%1,%2,%3};"
        : "+f"(c[0]), "+f"(c[1]), "+f"(c[2]), "+f"(c[3])
        : "r"(a0), "r"(a1), "r"(a2), "r"(a3), "r"(b0), "r"(b1));
}

__device__ __forceinline__ __nv_bfloat162 pack2(float a, float b)
{
    __nv_bfloat162 r;
    r.x = __float2bfloat16(a);
    r.y = __float2bfloat16(b);
    return r;
}

// ---------------- software grid barrier (used ONCE, after state init) ----------
__device__ __forceinline__ void gridsync(unsigned &gen, int nblk)
{
    __syncthreads();
    if (threadIdx.x == 0) {
        gen++;
        __threadfence();
        unsigned arrived = atomicAdd(&g_barCount, 1u) + 1u;
        if (arrived == (unsigned)nblk) {
            atomicExch(&g_barCount, 0u);
            __threadfence();
            atomicExch(&g_barGen, gen);
        } else {
            while (*((volatile unsigned*)&g_barGen) < gen) { }
        }
        __threadfence();
    }
    __syncthreads();
}

__device__ __forceinline__ void waitCounter(unsigned* ctr, unsigned base, unsigned target)
{
    if (threadIdx.x == 0) {
        while (*((volatile unsigned*)ctr) - base < target) { }
        __threadfence();
    }
    __syncthreads();
}

__device__ __forceinline__ void waitCounter2(unsigned* cx, unsigned bx, unsigned tx_,
                                             unsigned* cy, unsigned by, unsigned ty_)
{
    if (threadIdx.x == 0) {
        for (;;) {
            unsigned vx = *((volatile unsigned*)cx);
            unsigned vy = *((volatile unsigned*)cy);
            if (vx - bx >= tx_ && vy - by >= ty_) break;
        }
        __threadfence();
    }
    __syncthreads();
}

__device__ __forceinline__ void signalCtr(unsigned* ctr)
{
    __syncthreads();
    if (threadIdx.x == 0) { __threadfence(); atomicAdd(ctr, 1u); }
}

// ---------------- transpose W_ih0 -> g_WT0 [k][n]  (preA operand) -------------
__global__ void transposeW0(const float* __restrict__ src)   // src: [HID][INDIM]
{
    __shared__ float sm[32][33];
    int k0 = blockIdx.x * 32, c0 = blockIdx.y * 32;
    int tx = threadIdx.x, ty = threadIdx.y;   // 32 x 8
#pragma unroll
    for (int i = 0; i < 32; i += 8)
        sm[ty + i][tx] = src[(size_t)(c0 + ty + i) * INDIM + k0 + tx];
    __syncthreads();
#pragma unroll
    for (int i = 0; i < 32; i += 8)
        g_WT0[(size_t)(k0 + ty + i) * HID + c0 + tx] = sm[tx][ty + i];
}

// ---------------- build fused bf16 hi/lo weight fragments ---------------------
// index = ((nt*64 + kt)*32 + lane); entry uint4{hi_b0, hi_b1, lo_b0, lo_b1}.
// b0 covers { W[n][k], W[n][k+1] }, b1 { W[n][k+8], W[n][k+9] },
// n = nt*8 + lane/4, k = kt*16 + (lane%4)*2.
// Rows: n<1024 -> W_hh0, n<2048 -> W_ih1, else W_hh1.
__global__ void makeWfrag(const float* __restrict__ w_hh0,
                          const float* __restrict__ w_ih1,
                          const float* __restrict__ w_hh1)
{
    int id = blockIdx.x * 256 + threadIdx.x;        // [0, 384*64*32)
    int lane = id & 31;
    int kt = (id >> 5) & 63;
    int nt = id >> 11;
    int n = nt * 8 + (lane >> 2);
    int k = kt * 16 + (lane & 3) * 2;
    const float* W = (n < 1024) ? w_hh0 + (size_t)n * HID
                   : (n < 2048) ? w_ih1 + (size_t)(n - 1024) * HID
                                : w_hh1 + (size_t)(n - 2048) * HID;
    float w0 = W[k], w1 = W[k + 1], w2 = W[k + 8], w3 = W[k + 9];
    __nv_bfloat162 h0 = pack2(w0, w1), h1 = pack2(w2, w3);
    float l0 = w0 - __bfloat162float(h0.x), l1 = w1 - __bfloat162float(h0.y);
    float l2 = w2 - __bfloat162float(h1.x), l3 = w3 - __bfloat162float(h1.y);
    __nv_bfloat162 q0 = pack2(l0, l1), q1 = pack2(l2, l3);
    g_Wfrag[id] = make_uint4(*(uint32*)&h0, *(uint32*)&h1,
                             *(uint32*)&q0, *(uint32*)&q1);
}

// ---------------- preA = x @ W_ih0^T + (b_ih0 + b_hh0) ----------------
__global__ void __launch_bounds__(256) preA_gemm(const float* __restrict__ x,
                                                 const float* __restrict__ bih,
                                                 const float* __restrict__ bhh)
{
    __shared__ float Xs[64][33];
    __shared__ float Ws[32][64];
    const int m0 = blockIdx.y * 64;
    const int n0 = blockIdx.x * 64;
    const int tid = threadIdx.x;
    const int tx = tid & 15, ty = tid >> 4;

    ull acc[4][2];
#pragma unroll
    for (int i = 0; i < 4; i++) { acc[i][0] = 0ull; acc[i][1] = 0ull; }

    for (int kt = 0; kt < INDIM; kt += 32) {
        {
            int kq = (tid & 7) * 4, m = tid >> 3;
#pragma unroll
            for (int p = 0; p < 2; p++) {
                float4 v = *(const float4*)&x[(size_t)(m0 + m + p * 32) * INDIM + kt + kq];
                Xs[m + p * 32][kq + 0] = v.x; Xs[m + p * 32][kq + 1] = v.y;
                Xs[m + p * 32][kq + 2] = v.z; Xs[m + p * 32][kq + 3] = v.w;
            }
        }
        {
            int n4 = (tid & 15) * 4, kk = tid >> 4;
#pragma unroll
            for (int p = 0; p < 2; p++) {
                float4 v = *(const float4*)&g_WT0[(size_t)(kt + kk + p * 16) * HID + n0 + n4];
                *(float4*)&Ws[kk + p * 16][n4] = v;
            }
        }
        __syncthreads();
#pragma unroll
        for (int kk = 0; kk < 32; kk++) {
            ulonglong2 bw = *(const ulonglong2*)&Ws[kk][tx * 4];
#pragma unroll
            for (int i = 0; i < 4; i++) {
                ull ad = dup2(Xs[ty * 4 + i][kk]);
                acc[i][0] = fma2(ad, bw.x, acc[i][0]);
                acc[i][1] = fma2(ad, bw.y, acc[i][1]);
            }
        }
        __syncthreads();
    }
    const int c0 = n0 + tx * 4;
    float4 bi = *(const float4*)&bih[c0];
    float4 bh = *(const float4*)&bhh[c0];
    float4 b0 = make_float4(bi.x + bh.x, bi.y + bh.y, bi.z + bh.z, bi.w + bh.w);
#pragma unroll
    for (int i = 0; i < 4; i++) {
        int row = m0 + ty * 4 + i;
        float2 a01 = *(float2*)&acc[i][0];
        float2 a23 = *(float2*)&acc[i][1];
        float4 o = make_float4(a01.x + b0.x, a01.y + b0.y, a23.x + b0.z, a23.y + b0.w);
        *(float4*)&g_preA[(size_t)row * HID + c0] = o;
    }
}

// ---------------- recurrent GEMM work item (bf16-split tensor-core, low-reg) ---
// item = cb*6 + ks.  cb in [0,24): 128 strip-columns.  ks in [0,6): k-segment.
// cb 0..7: W_hh0 (h0);  cb 8..15: W_ih1 (h0);  cb 16..23: W_hh1 (h1).
// 3-pass bf16 split: D = Ahi*Bhi + Ahi*Blo + Alo*Bhi (fp32 accumulate).
// Warp layout: 8 warps = 4 m-tiles(16 rows) x 2 n-halves(64 cols).
// n-half processed in TWO passes of 4 n-tiles -> acc[4][4] (16 regs live),
// fused uint4 B-fragments -> half the mainloop LDG count. No spills.
template<int KLEN, bool ADDP>
__device__ __forceinline__ void gemm_item_t(__nv_bfloat16* s_hhi, __nv_bfloat16* s_hlo,
                                            float* pdst, int cb, int ks, int klo, int tn)
{
    const float* __restrict__ hs = (cb >= 16) ? g_h1 : g_h0;
    const int tid  = threadIdx.x;
    const int lane = tid & 31;
    const int warp = tid >> 5;
    const int qr = lane >> 2;           // 0..7
    const int qk = (lane & 3) * 2;      // 0,2,4,6
    const int m0 = (warp & 3) * 16;     // m-tile base (batch rows)
    const int nh = (warp >> 2) * 64;    // n-half within cb tile
    const int cbase = cb * 128 + nh;    // global strip col base for this warp

    // ---- stage h[0..63][klo..klo+KLEN) into smem as bf16 hi/lo planes ----
    constexpr int NF4   = KLEN / 4;
    constexpr int NPASS = (64 * NF4) / 256;   // 11 or 10
#pragma unroll
    for (int p = 0; p < NPASS; p++) {
        int idx = tid + p * 256;
        int row = idx / NF4;
        int col = (idx - row * NF4) * 4;      // bf16/float index within window
        float4 v = __ldcg((const float4*)&hs[row * HID + klo + col]);
        __nv_bfloat162 h01 = pack2(v.x, v.y), h23 = pack2(v.z, v.w);
        __nv_bfloat162 l01 = pack2(v.x - __bfloat162float(h01.x),
                                   v.y - __bfloat162float(h01.y));
        __nv_bfloat162 l23 = pack2(v.z - __bfloat162float(h23.x),
                                   v.w - __bfloat162float(h23.y));
        *(__nv_bfloat162*)&s_hhi[row * HSB + col]     = h01;
        *(__nv_bfloat162*)&s_hhi[row * HSB + col + 2] = h23;
        *(__nv_bfloat162*)&s_hlo[row * HSB + col]     = l01;
        *(__nv_bfloat162*)&s_hlo[row * HSB + col + 2] = l23;
    }
    __syncthreads();

    constexpr int NF16 = KLEN / 16;           // 11 or 10
    const int ktg0 = klo / 16;                // global k-tile base
    const int ntg0 = cb * 16 + (nh >> 3);     // global n-tile base for this warp

#pragma unroll 1
    for (int np = 0; np < 2; np++) {
        const int ntb = np * 4;               // n-tile offset within this warp's half

        // early-issue preA loads for this pass (ADDP only; 16 regs)
        float2 paL[4], paH[4];
        if (ADDP) {
#pragma unroll
            for (int nt = 0; nt < 4; nt++) {
                const float* pb = &g_preA[((size_t)tn * BATCH) * HID
                                          + cbase + (ntb + nt) * 8 + qk];
                paL[nt] = __ldcg((const float2*)&pb[(size_t)(m0 + qr) * HID]);
                paH[nt] = __ldcg((const float2*)&pb[(size_t)(m0 + qr + 8) * HID]);
            }
        }

        float acc[4][4];
#pragma unroll
        for (int nt = 0; nt < 4; nt++)
#pragma unroll
            for (int j = 0; j < 4; j++) acc[nt][j] = 0.0f;

#pragma unroll 1
        for (int kt = 0; kt < NF16; kt++) {
            const int kk = kt * 16;
            uint32 a0h = *(const uint32*)&s_hhi[(m0 + qr) * HSB + kk + qk];
            uint32 a1h = *(const uint32*)&s_hhi[(m0 + qr + 8) * HSB + kk + qk];
            uint32 a2h = *(const uint32*)&s_hhi[(m0 + qr) * HSB + kk + qk + 8];
            uint32 a3h = *(const uint32*)&s_hhi[(m0 + qr + 8) * HSB + kk + qk + 8];
            uint32 a0l = *(const uint32*)&s_hlo[(m0 + qr) * HSB + kk + qk];
            uint32 a1l = *(const uint32*)&s_hlo[(m0 + qr + 8) * HSB + kk + qk];
            uint32 a2l = *(const uint32*)&s_hlo[(m0 + qr) * HSB + kk + qk + 8];
            uint32 a3l = *(const uint32*)&s_hlo[(m0 + qr + 8) * HSB + kk + qk + 8];
            const size_t fbase = ((size_t)(ntg0 + ntb) * NTILES_K + (ktg0 + kt)) * 32 + lane;
#pragma unroll
            for (int nt = 0; nt < 4; nt++) {
                uint4 f = __ldg(&g_Wfrag[fbase + (size_t)nt * NTILES_K * 32]);
                mma_bf16(acc[nt], a0h, a1h, a2h, a3h, f.x, f.y);   // hi*hi
                mma_bf16(acc[nt], a0h, a1h, a2h, a3h, f.z, f.w);   // hi*lo
                mma_bf16(acc[nt], a0l, a1l, a2l, a3l, f.x, f.y);   // lo*hi
            }
        }

        // epilogue for this pass's 4 n-tiles
#pragma unroll
        for (int nt = 0; nt < 4; nt++) {
            float2 s0 = make_float2(acc[nt][0], acc[nt][1]);
            float2 s1 = make_float2(acc[nt][2], acc[nt][3]);
            if (ADDP) {
                s0.x += paL[nt].x; s0.y += paL[nt].y;
                s1.x += paH[nt].x; s1.y += paH[nt].y;
            }
            float* pb = &pdst[(size_t)(ks * BATCH) * STRIPS + cbase + (ntb + nt) * 8 + qk];
            __stcg((float2*)&pb[(size_t)(m0 + qr) * STRIPS], s0);
            __stcg((float2*)&pb[(size_t)(m0 + qr + 8) * STRIPS], s1);
        }
    }
    // signalCtr's __syncthreads guards restaging and orders all stores
}

__device__ __forceinline__ void gemm_item(int item, int tn, int par)
{
    // single smem instance shared by all template instantiations (47,104 B)
    __shared__ __nv_bfloat16 s_hhi[64 * HSB];
    __shared__ __nv_bfloat16 s_hlo[64 * HSB];
    float* pdst = g_parts + (size_t)par * PSTRIDE;

    const int cb = item / 6;
    const int ks = item - cb * 6;
    if (ks < 4) {
        if (cb < 8 && ks == 0) gemm_item_t<176, true >(s_hhi, s_hlo, pdst, cb, ks, 0, tn);
        else                   gemm_item_t<176, false>(s_hhi, s_hlo, pdst, cb, ks, ks * 176, tn);
    } else {
        gemm_item_t<160, false>(s_hhi, s_hlo, pdst, cb, ks, 704 + (ks - 4) * 160, tn);
    }
}

// ---------------- block-wide reduction (sum, sumsq) over 256 threads ----------------
__device__ __forceinline__ void blockReduce2(float &s1, float &s2)
{
    __shared__ float sm[16];
#pragma unroll
    for (int o = 16; o > 0; o >>= 1) {
        s1 += __shfl_down_sync(0xffffffffu, s1, o);
        s2 += __shfl_down_sync(0xffffffffu, s2, o);
    }
    int w = threadIdx.x >> 5, l = threadIdx.x & 31;
    if (l == 0) { sm[w] = s1; sm[8 + w] = s2; }
    __syncthreads();
    float a = 0.0f, b = 0.0f;
#pragma unroll
    for (int i = 0; i < 8; i++) { a += sm[i]; b += sm[8 + i]; }
    __syncthreads();
    s1 = a; s2 = b;
}

// ---------------- LayerNorm + tanh, layer 0 row ----------------
__device__ __forceinline__ void ln_row0(int r, int par,
                                        const float* __restrict__ lnw,
                                        const float* __restrict__ lnb)
{
    const float* pb = g_parts + (size_t)par * PSTRIDE;
    const int c = threadIdx.x * 4;
    float4 w = *(const float4*)&lnw[c];
    float4 b = *(const float4*)&lnb[c];
    float4 v = __ldcg((const float4*)&pb[(size_t)r * STRIPS + c]);  // ks = 0 (has preA)
#pragma unroll
    for (int ks = 1; ks < NKSEG; ks++) {
        float4 p = __ldcg((const float4*)&pb[(size_t)(ks * BATCH + r) * STRIPS + c]);
        v.x += p.x; v.y += p.y; v.z += p.z; v.w += p.w;
    }
    float s1 = v.x + v.y + v.z + v.w;
    float s2 = v.x * v.x + v.y * v.y + v.z * v.z + v.w * v.w;
    blockReduce2(s1, s2);
    float mu  = s1 * (1.0f / HID);
    float var = s2 * (1.0f / HID) - mu * mu;
    float rstd = rsqrtf(var + 1e-5f);
    float4 h;
    h.x = tanhf((v.x - mu) * rstd * w.x + b.x);
    h.y = tanhf((v.y - mu) * rstd * w.y + b.y);
    h.z = tanhf((v.z - mu) * rstd * w.z + b.z);
    h.w = tanhf((v.w - mu) * rstd * w.w + b.w);
    __stcg((float4*)&g_h0[r * HID + c], h);
}

// ---------------- LayerNorm + tanh, layer 1 row (also writes out[t]) ----------------
__device__ __forceinline__ void ln_row1(int t, int r, int par,
                                        const float* __restrict__ bi,
                                        const float* __restrict__ bh,
                                        const float* __restrict__ lnw,
                                        const float* __restrict__ lnb,
                                        float* __restrict__ out)
{
    const float* pb = g_parts + (size_t)par * PSTRIDE;
    const int c = threadIdx.x * 4;
    float4 a = *(const float4*)&bi[c];
    float4 d = *(const float4*)&bh[c];
    float4 w = *(const float4*)&lnw[c];
    float4 b = *(const float4*)&lnb[c];
    float4 v = make_float4(a.x + d.x, a.y + d.y, a.z + d.z, a.w + d.w);
#pragma unroll
    for (int ks = 0; ks < NKSEG; ks++) {
        float4 p = __ldcg((const float4*)&pb[(size_t)(ks * BATCH + r) * STRIPS + 1024 + c]);
        float4 q = __ldcg((const float4*)&pb[(size_t)(ks * BATCH + r) * STRIPS + 2048 + c]);
        v.x += p.x + q.x; v.y += p.y + q.y; v.z += p.z + q.z; v.w += p.w + q.w;
    }
    float s1 = v.x + v.y + v.z + v.w;
    float s2 = v.x * v.x + v.y * v.y + v.z * v.z + v.w * v.w;
    blockReduce2(s1, s2);
    float mu  = s1 * (1.0f / HID);
    float var = s2 * (1.0f / HID) - mu * mu;
    float rstd = rsqrtf(var + 1e-5f);
    float4 h;
    h.x = tanhf((v.x - mu) * rstd * w.x + b.x);
    h.y = tanhf((v.y - mu) * rstd * w.y + b.y);
    h.z = tanhf((v.z - mu) * rstd * w.z + b.z);
    h.w = tanhf((v.w - mu) * rstd * w.w + b.w);
    __stcg((float4*)&g_h1[r * HID + c], h);
    *(float4*)&out[((size_t)t * BATCH + r) * HID + c] = h;
}

// ---------------- persistent recurrent kernel (barrier-free pipeline) ---------
// (protocol identical to the audited version that has passed twice)
__global__ void __launch_bounds__(256, 1) rnn_persist(
    const float* __restrict__ hidden,
    const float* __restrict__ b_ih1, const float* __restrict__ b_hh1,
    const float* __restrict__ lnw0,  const float* __restrict__ lnb0,
    const float* __restrict__ lnw1,  const float* __restrict__ lnb1,
    float* __restrict__ out, int nblk)
{
    unsigned gen = 0, dAb = 0, dBb = 0, dL0b = 0, dL1b = 0;
    if (threadIdx.x == 0) {
        gen  = *((volatile unsigned*)&g_barGen);
        dAb  = *((volatile unsigned*)&g_doneA);
        dBb  = *((volatile unsigned*)&g_doneB);
        dL0b = *((volatile unsigned*)&g_doneL0);
        dL1b = *((volatile unsigned*)&g_doneL1);
    }
    const int bid = blockIdx.x;

    for (int i = bid * 256 + threadIdx.x; i < 2 * BATCH * HID; i += nblk * 256) {
        float v = hidden[i];
        if (i < BATCH * HID) __stcg(&g_h0[i], v);
        else                 __stcg(&g_h1[i - BATCH * HID], v);
    }
    gridsync(gen, nblk);

    // prologue: pre0(0) (items 0..47, parity 1)
    if (bid < 48) {
        gemm_item(bid, 0, 1);
        signalCtr(&g_doneA);
    }
    if (bid < 64) {
        waitCounter(&g_doneA, dAb, 48u);
        ln_row0(bid, 1, lnw0, lnb0);
        signalCtr(&g_doneL0);
    }

    for (int t = 0; t < T_STEPS; t++) {
        const int par = t & 1;
        const bool last = (t == T_STEPS - 1);

        if (bid < NITEMS && !(last && bid < 48)) {
            const int cb = bid / 6;
            if (cb < 8) {
                waitCounter(&g_doneL0, dL0b, 64u * (unsigned)(t + 1));
            } else if (cb < 16) {
                waitCounter2(&g_doneL0, dL0b, 64u * (unsigned)(t + 1),
                             &g_doneL1, dL1b, (t >= 1) ? 64u * (unsigned)(t - 1) : 0u);
            } else {
                waitCounter(&g_doneL1, dL1b, 64u * (unsigned)t);
            }
            gemm_item(bid, t + 1, par);
            signalCtr(bid < 96 ? &g_doneA : &g_doneB);
        }

        if (bid < 64) {
            if (!last) {
                waitCounter(&g_doneA, dAb, 48u + 96u * (unsigned)(t + 1));
                ln_row0(bid, par, lnw0, lnb0);
                signalCtr(&g_doneL0);
            }
        } else if (bid < 128) {
            waitCounter2(&g_doneA, dAb, 48u + 96u * (unsigned)t + (last ? 48u : 96u),
                         &g_doneB, dBb, 48u * (unsigned)(t + 1));
            ln_row1(t, bid - 64, par, b_ih1, b_hh1, lnw1, lnb1, out);
            signalCtr(&g_doneL1);
        }
    }

    waitCounter2(&g_doneL0, dL0b, 64u * (unsigned)T_STEPS,
                 &g_doneL1, dL1b, 64u * (unsigned)T_STEPS);
    const size_t tail = (size_t)T_STEPS * BATCH * HID;
    for (int i = bid * 256 + threadIdx.x; i < BATCH * HID; i += nblk * 256) {
        out[tail + i]               = __ldcg(&g_h0[i]);
        out[tail + BATCH * HID + i] = __ldcg(&g_h1[i]);
    }
}

// ---------------- host launcher ----------------
extern "C" void kernel_launch(void* const* d_in, const int* in_sizes, int n_in,
                              void* d_out, int out_size)
{
    const float* input = (const float*)d_in[0];
    const float* hidden = (const float*)d_in[1];
    const float* W_ih0 = (const float*)d_in[2];
    const float* W_hh0 = (const float*)d_in[3];
    const float* b_ih0 = (const float*)d_in[4];
    const float* b_hh0 = (const float*)d_in[5];
    const float* ln_w0 = (const float*)d_in[6];
    const float* ln_b0 = (const float*)d_in[7];
    const float* W_ih1 = (const float*)d_in[8];
    const float* W_hh1 = (const float*)d_in[9];
    const float* b_ih1 = (const float*)d_in[10];
    const float* b_hh1 = (const float*)d_in[11];
    const float* ln_w1 = (const float*)d_in[12];
    const float* ln_b1 = (const float*)d_in[13];
    float* out = (float*)d_out;

    int dev = 0, nsm = 148;
    cudaGetDevice(&dev);
    cudaDeviceGetAttribute(&nsm, cudaDevAttrMultiProcessorCount, dev);

    // 1) weight prep: transpose W_ih0 (preA) + fused bf16 fragments (recurrent)
    transposeW0<<<dim3(INDIM / 32, HID / 32), dim3(32, 8)>>>(W_ih0);
    makeWfrag<<<(NTILES_N * NTILES_K * 32) / 256, 256>>>(W_hh0, W_ih1, W_hh1);

    // 2) preA = x @ W_ih0^T + b0 for all timesteps (parallel GEMM)
    preA_gemm<<<dim3(HID / 64, (T_STEPS * BATCH) / 64), 256>>>(input, b_ih0, b_hh0);

    // 3) persistent recurrent kernel
    rnn_persist<<<nsm, 256>>>(hidden, b_ih1, b_hh1, ln_w0, ln_b0, ln_w1, ln_b1, out, nsm);
}